// round 14
// baseline (speedup 1.0000x reference)
#include <cuda_runtime.h>

// Problem shapes (fixed by the reference)
#define BB 4
#define QQ 128
#define KK 1024
#define HH 256
#define QS 256
#define KSZ 256
#define DV 256
#define SPLITS 16         // flash split-K factor (strided k assignment)
#define QTILE 32          // q's per flash CTA (lane = q)
#define KPC 64            // k's per flash CTA (= KK/SPLITS), 8 warps x 8
#define PPAD 68           // s_p row stride (q-major), multiple of 4
#define PM 128            // proj tile M
#define PN 32             // proj tile N
#define PBK 32            // proj tile K

// Scratch (alloc-free rule: __device__ globals)
__device__ float g_qproj[BB * QQ * HH];                 // [B,Q,H]
__device__ float g_kproj[BB * KK * HH];                 // [B,K,H]
__device__ float g_Opart[SPLITS * BB * QQ * DV];        // per-split partial outputs
__device__ float g_mpart[SPLITS * BB * QQ];             // per-split row max
__device__ float g_Spart[SPLITS * BB * QQ];             // per-split exp-sum

// Robust valid_lens decode: reference says int64 but may materialize int32.
// valid_lens >= 1 always, so int64-LE viewed as int32 has zeros at odd slots.
__device__ __forceinline__ int load_vlen(const int* vl32, int b) {
    bool is64 = (vl32[1] == 0) && (vl32[3] == 0);
    return is64 ? vl32[2 * b] : vl32[b];
}

__device__ __forceinline__ float tanh_approx(float x) {
    float y;
    asm("tanh.approx.f32 %0, %1;" : "=f"(y) : "f"(x));
    return y;
}

// ---------------------------------------------------------------------------
// Projection GEMM: 128(M) x 32(N) tile, BK=32, 256 threads, 4x4 microtile.
// As stored transposed (As[kk][row]); 2x LDS.128 per 16 FMA; 8 sync windows.
// grid (HH/32=8, 4+32=36) = 288 CTAs -> ~2 CTAs/SM.
// ---------------------------------------------------------------------------
__device__ __forceinline__ void gemm_body(const float* __restrict__ A,
                                          const float* __restrict__ Bm,
                                          float* __restrict__ C,
                                          int N, int K, int m0, int n0) {
    __shared__ float As[PBK][132];   // [kk][row]
    __shared__ float Bs[PBK][PN];    // [kk][col]

    const int tid = threadIdx.x;
    const int tx = tid & 7;          // 8 -> 4 cols each
    const int ty = tid >> 3;         // 32 -> 4 rows each

    float acc[4][4] = {};
    float a_reg[16], b_reg[4];

    // prefetch first tiles (A: 128x32 = 4096 -> 16/thread; B: 32x32 -> 4/thread)
#pragma unroll
    for (int i = 0; i < 16; i++) {
        int idx = tid + i * 256;
        a_reg[i] = A[(size_t)(m0 + (idx >> 5)) * K + (idx & 31)];
    }
#pragma unroll
    for (int i = 0; i < 4; i++) {
        int idx = tid + i * 256;
        b_reg[i] = Bm[(size_t)(idx >> 5) * N + (n0 + (idx & 31))];
    }

    for (int k0 = 0; k0 < K; k0 += PBK) {
#pragma unroll
        for (int i = 0; i < 16; i++) {
            int idx = tid + i * 256;
            As[idx & 31][idx >> 5] = a_reg[i];   // transposed store
        }
#pragma unroll
        for (int i = 0; i < 4; i++) {
            int idx = tid + i * 256;
            Bs[idx >> 5][idx & 31] = b_reg[i];
        }
        __syncthreads();

        if (k0 + PBK < K) {
#pragma unroll
            for (int i = 0; i < 16; i++) {
                int idx = tid + i * 256;
                a_reg[i] = A[(size_t)(m0 + (idx >> 5)) * K + (k0 + PBK + (idx & 31))];
            }
#pragma unroll
            for (int i = 0; i < 4; i++) {
                int idx = tid + i * 256;
                b_reg[i] = Bm[(size_t)(k0 + PBK + (idx >> 5)) * N + (n0 + (idx & 31))];
            }
        }

#pragma unroll
        for (int kk = 0; kk < PBK; kk++) {
            float4 av = *(const float4*)&As[kk][ty * 4];
            float4 bv = *(const float4*)&Bs[kk][tx * 4];
            float a[4] = {av.x, av.y, av.z, av.w};
            float b[4] = {bv.x, bv.y, bv.z, bv.w};
#pragma unroll
            for (int i = 0; i < 4; i++)
#pragma unroll
                for (int j = 0; j < 4; j++)
                    acc[i][j] = fmaf(a[i], b[j], acc[i][j]);
        }
        __syncthreads();
    }

#pragma unroll
    for (int i = 0; i < 4; i++) {
        float4 v = {acc[i][0], acc[i][1], acc[i][2], acc[i][3]};
        *(float4*)&C[(size_t)(m0 + ty * 4 + i) * N + (n0 + tx * 4)] = v;
    }
}

// Merged projections: blockIdx.y < 4 -> q-proj (M=512), else k-proj (M=4096).
__global__ void __launch_bounds__(256) gemm_proj_kernel(const float* __restrict__ queries,
                                                        const float* __restrict__ keys,
                                                        const float* __restrict__ Wq,
                                                        const float* __restrict__ Wk) {
    const int by = blockIdx.y;
    const int n0 = blockIdx.x * PN;
    if (by < (BB * QQ) / PM) {
        gemm_body(queries, Wq, g_qproj, HH, QS, by * PM, n0);
    } else {
        gemm_body(keys, Wk, g_kproj, HH, KSZ, (by - (BB * QQ) / PM) * PM, n0);
    }
}

// ---------------------------------------------------------------------------
// Fused flash partial: CTA = (split s, q-tile qt, batch b). grid (16,4,4).
// Split s owns k in {s, s+16, ...}; cnt = ceil((vlen-s)/16) contiguous in j.
// Phase 1: scores, lane-per-q, scalar tanh.approx.f32, active j only.
// Phase 2: per-q max / exp / partial sums. Phase 3: P @ V (smem reuse).
// ---------------------------------------------------------------------------
extern __shared__ float s_dyn[];

__global__ void __launch_bounds__(256) flash_kernel(const float* __restrict__ values,
                                                    const float* __restrict__ Wv,
                                                    const int* __restrict__ valid_lens32) {
    const int s = blockIdx.x;
    const int qt = blockIdx.y;
    const int b = blockIdx.z;
    const int tid = threadIdx.x;
    const int lane = tid & 31;
    const int wid = tid >> 5;

    // smem carve-up (floats)
    float* s_q = s_dyn;                          // 32*260 = 8320
    float* s_w = s_q + QTILE * 260;              // 256
    float* s_kv = s_w + 256;                     // 64*256 = 16384 (K, then V)
    float* s_p = s_kv + KPC * 256;               // 32*68 = 2176
    float* s_m = s_p + QTILE * PPAD;             // 8*32 = 256
    float* s_sig = s_m + 256;                    // 8*32 = 256
    float* s_mq = s_sig + 256;                   // 32

    const int vlen = load_vlen(valid_lens32, b);
    int cnt = (vlen - s + 15) >> 4;              // ceil((vlen-s)/16)
    if (cnt > KPC) cnt = KPC;

    const size_t prow = ((size_t)(s * BB + b)) * QQ + qt * QTILE;
    float* Obase = g_Opart + prow * DV;

    if (cnt <= 0) {   // whole split masked: emit neutral partial
#pragma unroll
        for (int q = 0; q < QTILE; q++) Obase[(size_t)q * DV + tid] = 0.0f;
        if (tid < QTILE) { g_mpart[prow + tid] = -1e30f; g_Spart[prow + tid] = 0.0f; }
        return;
    }

    // stage q tile (32x256) with pad-260 rows
    const float4* qbase = (const float4*)(g_qproj + ((size_t)(b * QQ + qt * QTILE)) * HH);
#pragma unroll
    for (int i = 0; i < 8; i++) {
        int idx = tid + i * 256;
        *(float4*)&s_q[(idx >> 6) * 260 + (idx & 63) * 4] = qbase[idx];
    }
    if (tid < 64) ((float4*)s_w)[tid] = ((const float4*)Wv)[tid];

    // stage K rows k = s + 16*j for ACTIVE j only
    const float4* kp = (const float4*)(g_kproj + ((size_t)b * KK) * HH);
#pragma unroll
    for (int i = 0; i < 16; i++) {
        int idx = tid + i * 256;
        int j = idx >> 6, c = idx & 63;
        if (j < cnt)
            *(float4*)&s_kv[j * 256 + c * 4] = kp[(size_t)(s + 16 * j) * 64 + c];
    }
    __syncthreads();   // A

    // Phase 1: scores. warp wid owns j = wid*8 .. +8; lane = q.
    const float* sqrow = s_q + lane * 260;
    const float* sk = s_kv + wid * (8 * 256);
    float acc[8] = {};
    const int rem = cnt - wid * 8;               // active j's for this warp

    if (rem >= 8) {
#pragma unroll 2
        for (int h4 = 0; h4 < 64; h4++) {
            float4 qv = *(const float4*)&sqrow[h4 * 4];
            float4 wv = *(const float4*)&s_w[h4 * 4];
#pragma unroll
            for (int jj = 0; jj < 8; jj++) {
                float4 kv = *(const float4*)&sk[jj * 256 + h4 * 4];
                float a = acc[jj];
                a = fmaf(tanh_approx(qv.x + kv.x), wv.x, a);
                a = fmaf(tanh_approx(qv.y + kv.y), wv.y, a);
                a = fmaf(tanh_approx(qv.z + kv.z), wv.z, a);
                a = fmaf(tanh_approx(qv.w + kv.w), wv.w, a);
                acc[jj] = a;
            }
        }
    } else if (rem > 0) {
#pragma unroll 2
        for (int h4 = 0; h4 < 64; h4++) {
            float4 qv = *(const float4*)&sqrow[h4 * 4];
            float4 wv = *(const float4*)&s_w[h4 * 4];
#pragma unroll
            for (int jj = 0; jj < 8; jj++) {
                if (jj < rem) {
                    float4 kv = *(const float4*)&sk[jj * 256 + h4 * 4];
                    float a = acc[jj];
                    a = fmaf(tanh_approx(qv.x + kv.x), wv.x, a);
                    a = fmaf(tanh_approx(qv.y + kv.y), wv.y, a);
                    a = fmaf(tanh_approx(qv.z + kv.z), wv.z, a);
                    a = fmaf(tanh_approx(qv.w + kv.w), wv.w, a);
                    acc[jj] = a;
                }
            }
        }
    }
    // rem <= 0: skip phase 1 entirely (acc stays 0, masked below)

    // Phase 2a: per-warp per-q max over valid j's
    float lmax = -1e30f;
#pragma unroll
    for (int jj = 0; jj < 8; jj++) {
        if (jj < rem) lmax = fmaxf(lmax, acc[jj]);
    }
    s_m[wid * 32 + lane] = lmax;
    __syncthreads();   // B

    if (wid == 0) {
        float m = s_m[lane];
#pragma unroll
        for (int w = 1; w < 8; w++) m = fmaxf(m, s_m[w * 32 + lane]);
        s_mq[lane] = m;
    }
    __syncthreads();   // C

    // Phase 2b: exp, partial sums, stage p (q-major)
    const float mq = s_mq[lane];
    float p[8];
    float sig = 0.0f;
#pragma unroll
    for (int jj = 0; jj < 8; jj++) {
        p[jj] = (jj < rem) ? __expf(acc[jj] - mq) : 0.0f;
        sig += p[jj];
    }
    s_sig[wid * 32 + lane] = sig;
    *(float4*)&s_p[lane * PPAD + wid * 8]     = make_float4(p[0], p[1], p[2], p[3]);
    *(float4*)&s_p[lane * PPAD + wid * 8 + 4] = make_float4(p[4], p[5], p[6], p[7]);
    __syncthreads();   // D (s_kv reads all done -> safe to overwrite below)

    if (wid == 0) {
        float S = s_sig[lane];
#pragma unroll
        for (int w = 1; w < 8; w++) S += s_sig[w * 32 + lane];
        g_mpart[prow + lane] = mq;
        g_Spart[prow + lane] = S;
    }

    // stage V rows k = s + 16*j into s_kv (reuse), ACTIVE j only
    const float4* vp = (const float4*)(values + ((size_t)b * KK) * DV);
#pragma unroll
    for (int i = 0; i < 16; i++) {
        int idx = tid + i * 256;
        int j = idx >> 6, c = idx & 63;
        if (j < cnt)
            *(float4*)&s_kv[j * 256 + c * 4] = vp[(size_t)(s + 16 * j) * 64 + c];
    }
    __syncthreads();   // E

    // Phase 3: O[q][dv] = sum_j p[q][j] * V[j][dv]. thread dv = wid*32+lane.
    const int dv = wid * 32 + lane;
    float v[KPC];
#pragma unroll
    for (int c = 0; c < 4; c++) {
        if (c * 16 < cnt) {
#pragma unroll
            for (int jj = 0; jj < 16; jj++) v[c * 16 + jj] = s_kv[(c * 16 + jj) * 256 + dv];
        }
    }

#pragma unroll 1
    for (int q = 0; q < QTILE; q++) {
        const float* pr = s_p + q * PPAD;
        float a0 = 0.f, a1 = 0.f, a2 = 0.f, a3 = 0.f;
#pragma unroll
        for (int c = 0; c < 4; c++) {
            if (c * 16 < cnt) {
#pragma unroll
                for (int j4 = c * 4; j4 < c * 4 + 4; j4++) {
                    float4 pv = *(const float4*)&pr[j4 * 4];
                    a0 = fmaf(pv.x, v[j4 * 4 + 0], a0);
                    a1 = fmaf(pv.y, v[j4 * 4 + 1], a1);
                    a2 = fmaf(pv.z, v[j4 * 4 + 2], a2);
                    a3 = fmaf(pv.w, v[j4 * 4 + 3], a3);
                }
            }
        }
        Obase[(size_t)q * DV + dv] = (a0 + a1) + (a2 + a3);
    }
}

// ---------------------------------------------------------------------------
// Combine: out[b][q][:] = sum_s e^{m_s-M} O_s / sum_s e^{m_s-M} S_s.
// grid (QQ, BB) = 512 CTAs, 256 threads (dv).
// ---------------------------------------------------------------------------
__global__ void __launch_bounds__(256) combine_kernel(float* __restrict__ out) {
    const int q = blockIdx.x;
    const int b = blockIdx.y;
    const int tid = threadIdx.x;

    __shared__ float s_wt[SPLITS];

    if (tid < 32) {
        float m = -1e30f, S = 0.0f;
        if (tid < SPLITS) {
            size_t pidx = ((size_t)(tid * BB + b)) * QQ + q;
            m = g_mpart[pidx];
            S = g_Spart[pidx];
        }
        float M = m;
#pragma unroll
        for (int off = 16; off; off >>= 1)
            M = fmaxf(M, __shfl_xor_sync(0xffffffffu, M, off));
        float e = (m > -1e29f) ? __expf(m - M) : 0.0f;
        float d = e * S;
#pragma unroll
        for (int off = 16; off; off >>= 1)
            d += __shfl_xor_sync(0xffffffffu, d, off);
        if (tid < SPLITS) s_wt[tid] = e * __fdividef(1.0f, d);
    }
    __syncthreads();

    float acc = 0.0f;
#pragma unroll
    for (int s = 0; s < SPLITS; s++) {
        acc = fmaf(s_wt[s], g_Opart[(((size_t)(s * BB + b)) * QQ + q) * DV + tid], acc);
    }
    out[((size_t)(b * QQ + q)) * DV + tid] = acc;
}

// ---------------------------------------------------------------------------
// Launch
// ---------------------------------------------------------------------------
extern "C" void kernel_launch(void* const* d_in, const int* in_sizes, int n_in,
                              void* d_out, int out_size) {
    const float* queries = (const float*)d_in[0];
    const float* keys    = (const float*)d_in[1];
    const float* values  = (const float*)d_in[2];
    const int*   valid_lens = (const int*)d_in[3];
    const float* Wq = (const float*)d_in[4];
    const float* Wk = (const float*)d_in[5];
    const float* Wv = (const float*)d_in[6];
    float* out = (float*)d_out;

    (void)in_sizes; (void)n_in; (void)out_size;

    const int smem_bytes = (QTILE * 260 + 256 + KPC * 256 + QTILE * PPAD + 256 + 256 + 32) * 4;
    cudaFuncSetAttribute(flash_kernel, cudaFuncAttributeMaxDynamicSharedMemorySize, smem_bytes);

    gemm_proj_kernel<<<dim3(HH / PN, (BB * QQ) / PM + (BB * KK) / PM), 256>>>(queries, keys, Wq, Wk);
    flash_kernel<<<dim3(SPLITS, QQ / QTILE, BB), 256, smem_bytes>>>(values, Wv, valid_lens);
    combine_kernel<<<dim3(QQ, BB), 256>>>(out);
}

// round 16
// speedup vs baseline: 1.1364x; 1.1364x over previous
#include <cuda_runtime.h>

// Problem shapes (fixed by the reference)
#define BB 4
#define QQ 128
#define KK 1024
#define HH 256
#define QS 256
#define KSZ 256
#define DV 256
#define SPLITS 32         // flash split-K factor (stride-32 k assignment)
#define QTILE 32          // q's per flash CTA (lane = q)
#define KPC 32            // k's per flash CTA (= KK/SPLITS), 8 warps x 4
#define JW 4              // j's per warp
#define PPAD 36           // s_p row stride (q-major), multiple of 4
#define PM 128            // proj tile M
#define PN 32             // proj tile N

// Scratch (alloc-free rule: __device__ globals)
__device__ float g_qproj[BB * QQ * HH];                 // [B,Q,H]
__device__ float g_kproj[BB * KK * HH];                 // [B,K,H]
__device__ float g_Opart[SPLITS * BB * QQ * DV];        // per-split partial outputs
__device__ float g_mpart[SPLITS * BB * QQ];             // per-split row max
__device__ float g_Spart[SPLITS * BB * QQ];             // per-split exp-sum

// Robust valid_lens decode: reference says int64 but may materialize int32.
// valid_lens >= 1 always, so int64-LE viewed as int32 has zeros at odd slots.
__device__ __forceinline__ int load_vlen(const int* vl32, int b) {
    bool is64 = (vl32[1] == 0) && (vl32[3] == 0);
    return is64 ? vl32[2 * b] : vl32[b];
}

__device__ __forceinline__ float tanh_approx(float x) {
    float y;
    asm("tanh.approx.f32 %0, %1;" : "=f"(y) : "f"(x));
    return y;
}

// ---------------------------------------------------------------------------
// Projection GEMM (R12 form): 128(M) x 32(N) tile, BK=16, 256 threads,
// 4x4 microtile, As transposed. grid (8, 36) = 288 CTAs.
// ---------------------------------------------------------------------------
__device__ __forceinline__ void gemm_body(const float* __restrict__ A,
                                          const float* __restrict__ Bm,
                                          float* __restrict__ C,
                                          int N, int K, int m0, int n0) {
    constexpr int BK = 16;
    __shared__ float As[BK][132];    // [kk][row]
    __shared__ float Bs[BK][PN];     // [kk][col]

    const int tid = threadIdx.x;
    const int tx = tid & 7;          // 8 -> 4 cols each
    const int ty = tid >> 3;         // 32 -> 4 rows each

    float acc[4][4] = {};
    float a_reg[8], b_reg[2];

#pragma unroll
    for (int i = 0; i < 8; i++) {
        int idx = tid + i * 256;
        a_reg[i] = A[(size_t)(m0 + (idx >> 4)) * K + (idx & 15)];
    }
#pragma unroll
    for (int i = 0; i < 2; i++) {
        int idx = tid + i * 256;
        b_reg[i] = Bm[(size_t)(idx >> 5) * N + (n0 + (idx & 31))];
    }

    for (int k0 = 0; k0 < K; k0 += BK) {
#pragma unroll
        for (int i = 0; i < 8; i++) {
            int idx = tid + i * 256;
            As[idx & 15][idx >> 4] = a_reg[i];   // transposed store
        }
#pragma unroll
        for (int i = 0; i < 2; i++) {
            int idx = tid + i * 256;
            Bs[idx >> 5][idx & 31] = b_reg[i];
        }
        __syncthreads();

        if (k0 + BK < K) {
#pragma unroll
            for (int i = 0; i < 8; i++) {
                int idx = tid + i * 256;
                a_reg[i] = A[(size_t)(m0 + (idx >> 4)) * K + (k0 + BK + (idx & 15))];
            }
#pragma unroll
            for (int i = 0; i < 2; i++) {
                int idx = tid + i * 256;
                b_reg[i] = Bm[(size_t)(k0 + BK + (idx >> 5)) * N + (n0 + (idx & 31))];
            }
        }

#pragma unroll
        for (int kk = 0; kk < BK; kk++) {
            float4 av = *(const float4*)&As[kk][ty * 4];
            float4 bv = *(const float4*)&Bs[kk][tx * 4];
            float a[4] = {av.x, av.y, av.z, av.w};
            float b[4] = {bv.x, bv.y, bv.z, bv.w};
#pragma unroll
            for (int i = 0; i < 4; i++)
#pragma unroll
                for (int j = 0; j < 4; j++)
                    acc[i][j] = fmaf(a[i], b[j], acc[i][j]);
        }
        __syncthreads();
    }

#pragma unroll
    for (int i = 0; i < 4; i++) {
        float4 v = {acc[i][0], acc[i][1], acc[i][2], acc[i][3]};
        *(float4*)&C[(size_t)(m0 + ty * 4 + i) * N + (n0 + tx * 4)] = v;
    }
}

// Merged projections: blockIdx.y < 4 -> q-proj (M=512), else k-proj (M=4096).
__global__ void __launch_bounds__(256) gemm_proj_kernel(const float* __restrict__ queries,
                                                        const float* __restrict__ keys,
                                                        const float* __restrict__ Wq,
                                                        const float* __restrict__ Wk) {
    const int by = blockIdx.y;
    const int n0 = blockIdx.x * PN;
    if (by < (BB * QQ) / PM) {
        gemm_body(queries, Wq, g_qproj, HH, QS, by * PM, n0);
    } else {
        gemm_body(keys, Wk, g_kproj, HH, KSZ, (by - (BB * QQ) / PM) * PM, n0);
    }
}

// ---------------------------------------------------------------------------
// Fused flash partial: CTA = (split s, q-tile qt, batch b). grid (32,4,4)=512.
// Split s owns k in {s, s+32, ...}; cnt = ceil((vlen-s)/32) <= 32, contiguous j.
// 8 warps x 4 j each; lane = q. smem ~72KB -> 3 CTAs/SM (launch_bounds 256,3).
// ---------------------------------------------------------------------------
extern __shared__ float s_dyn[];

__global__ void __launch_bounds__(256, 3) flash_kernel(const float* __restrict__ values,
                                                       const float* __restrict__ Wv,
                                                       const int* __restrict__ valid_lens32) {
    const int s = blockIdx.x;
    const int qt = blockIdx.y;
    const int b = blockIdx.z;
    const int tid = threadIdx.x;
    const int lane = tid & 31;
    const int wid = tid >> 5;

    // smem carve-up (floats)
    float* s_q = s_dyn;                          // 32*260 = 8320
    float* s_w = s_q + QTILE * 260;              // 256
    float* s_kv = s_w + 256;                     // 32*256 = 8192 (K, then V)
    float* s_p = s_kv + KPC * 256;               // 32*36 = 1152
    float* s_m = s_p + QTILE * PPAD;             // 8*32 = 256
    float* s_sig = s_m + 256;                    // 8*32 = 256
    float* s_mq = s_sig + 256;                   // 32

    const int vlen = load_vlen(valid_lens32, b);
    int cnt = (vlen - s + SPLITS - 1) / SPLITS;  // ceil((vlen-s)/32)
    if (cnt > KPC) cnt = KPC;

    const size_t prow = ((size_t)(s * BB + b)) * QQ + qt * QTILE;
    float* Obase = g_Opart + prow * DV;

    if (cnt <= 0) {   // whole split masked (vlen <= s): emit neutral partial
#pragma unroll
        for (int q = 0; q < QTILE; q++) Obase[(size_t)q * DV + tid] = 0.0f;
        if (tid < QTILE) { g_mpart[prow + tid] = -1e30f; g_Spart[prow + tid] = 0.0f; }
        return;
    }

    // stage q tile (32x256) with pad-260 rows
    const float4* qbase = (const float4*)(g_qproj + ((size_t)(b * QQ + qt * QTILE)) * HH);
#pragma unroll
    for (int i = 0; i < 8; i++) {
        int idx = tid + i * 256;
        *(float4*)&s_q[(idx >> 6) * 260 + (idx & 63) * 4] = qbase[idx];
    }
    if (tid < 64) ((float4*)s_w)[tid] = ((const float4*)Wv)[tid];

    // stage K rows k = s + 32*j for ACTIVE j only (32 rows x 64 float4)
    const float4* kp = (const float4*)(g_kproj + ((size_t)b * KK) * HH);
#pragma unroll
    for (int i = 0; i < 8; i++) {
        int idx = tid + i * 256;
        int j = idx >> 6, c = idx & 63;
        if (j < cnt)
            *(float4*)&s_kv[j * 256 + c * 4] = kp[(size_t)(s + SPLITS * j) * 64 + c];
    }
    __syncthreads();   // A

    // Phase 1: scores. warp wid owns j = wid*4 .. +4; lane = q.
    const float* sqrow = s_q + lane * 260;
    const float* sk = s_kv + wid * (JW * 256);
    float acc[JW] = {};
    const int rem = cnt - wid * JW;              // active j's for this warp

    if (rem >= JW) {
#pragma unroll 2
        for (int h4 = 0; h4 < 64; h4++) {
            float4 qv = *(const float4*)&sqrow[h4 * 4];
            float4 wv = *(const float4*)&s_w[h4 * 4];
#pragma unroll
            for (int jj = 0; jj < JW; jj++) {
                float4 kv = *(const float4*)&sk[jj * 256 + h4 * 4];
                float a = acc[jj];
                a = fmaf(tanh_approx(qv.x + kv.x), wv.x, a);
                a = fmaf(tanh_approx(qv.y + kv.y), wv.y, a);
                a = fmaf(tanh_approx(qv.z + kv.z), wv.z, a);
                a = fmaf(tanh_approx(qv.w + kv.w), wv.w, a);
                acc[jj] = a;
            }
        }
    } else if (rem > 0) {
#pragma unroll 2
        for (int h4 = 0; h4 < 64; h4++) {
            float4 qv = *(const float4*)&sqrow[h4 * 4];
            float4 wv = *(const float4*)&s_w[h4 * 4];
#pragma unroll
            for (int jj = 0; jj < JW; jj++) {
                if (jj < rem) {
                    float4 kv = *(const float4*)&sk[jj * 256 + h4 * 4];
                    float a = acc[jj];
                    a = fmaf(tanh_approx(qv.x + kv.x), wv.x, a);
                    a = fmaf(tanh_approx(qv.y + kv.y), wv.y, a);
                    a = fmaf(tanh_approx(qv.z + kv.z), wv.z, a);
                    a = fmaf(tanh_approx(qv.w + kv.w), wv.w, a);
                    acc[jj] = a;
                }
            }
        }
    }

    // Phase 2a: per-warp per-q max over valid j's
    float lmax = -1e30f;
#pragma unroll
    for (int jj = 0; jj < JW; jj++) {
        if (jj < rem) lmax = fmaxf(lmax, acc[jj]);
    }
    s_m[wid * 32 + lane] = lmax;
    __syncthreads();   // B

    if (wid == 0) {
        float m = s_m[lane];
#pragma unroll
        for (int w = 1; w < 8; w++) m = fmaxf(m, s_m[w * 32 + lane]);
        s_mq[lane] = m;
    }
    __syncthreads();   // C

    // Phase 2b: exp, partial sums, stage p (q-major)
    const float mq = s_mq[lane];
    float p[JW];
    float sig = 0.0f;
#pragma unroll
    for (int jj = 0; jj < JW; jj++) {
        p[jj] = (jj < rem) ? __expf(acc[jj] - mq) : 0.0f;
        sig += p[jj];
    }
    s_sig[wid * 32 + lane] = sig;
    *(float4*)&s_p[lane * PPAD + wid * JW] = make_float4(p[0], p[1], p[2], p[3]);
    __syncthreads();   // D (s_kv reads all done -> safe to overwrite below)

    if (wid == 0) {
        float S = s_sig[lane];
#pragma unroll
        for (int w = 1; w < 8; w++) S += s_sig[w * 32 + lane];
        g_mpart[prow + lane] = mq;
        g_Spart[prow + lane] = S;
    }

    // stage V rows k = s + 32*j into s_kv (reuse), ACTIVE j only
    const float4* vp = (const float4*)(values + ((size_t)b * KK) * DV);
#pragma unroll
    for (int i = 0; i < 8; i++) {
        int idx = tid + i * 256;
        int j = idx >> 6, c = idx & 63;
        if (j < cnt)
            *(float4*)&s_kv[j * 256 + c * 4] = vp[(size_t)(s + SPLITS * j) * 64 + c];
    }
    __syncthreads();   // E

    // Phase 3: O[q][dv] = sum_j p[q][j] * V[j][dv]. thread dv = wid*32+lane.
    const int dv = wid * 32 + lane;
    float v[KPC];
#pragma unroll
    for (int c = 0; c < 2; c++) {
        if (c * 16 < cnt) {
#pragma unroll
            for (int jj = 0; jj < 16; jj++) v[c * 16 + jj] = s_kv[(c * 16 + jj) * 256 + dv];
        }
    }

#pragma unroll 1
    for (int q = 0; q < QTILE; q++) {
        const float* pr = s_p + q * PPAD;
        float a0 = 0.f, a1 = 0.f, a2 = 0.f, a3 = 0.f;
#pragma unroll
        for (int c = 0; c < 2; c++) {
            if (c * 16 < cnt) {
#pragma unroll
                for (int j4 = c * 4; j4 < c * 4 + 4; j4++) {
                    float4 pv = *(const float4*)&pr[j4 * 4];
                    a0 = fmaf(pv.x, v[j4 * 4 + 0], a0);
                    a1 = fmaf(pv.y, v[j4 * 4 + 1], a1);
                    a2 = fmaf(pv.z, v[j4 * 4 + 2], a2);
                    a3 = fmaf(pv.w, v[j4 * 4 + 3], a3);
                }
            }
        }
        Obase[(size_t)q * DV + dv] = (a0 + a1) + (a2 + a3);
    }
}

// ---------------------------------------------------------------------------
// Combine: out[b][q][:] = sum_s e^{m_s-M} O_s / sum_s e^{m_s-M} S_s.
// grid (QQ, BB) = 512 CTAs, 256 threads (dv).
// ---------------------------------------------------------------------------
__global__ void __launch_bounds__(256) combine_kernel(float* __restrict__ out) {
    const int q = blockIdx.x;
    const int b = blockIdx.y;
    const int tid = threadIdx.x;

    __shared__ float s_wt[SPLITS];

    if (tid < 32) {
        size_t pidx = ((size_t)(tid * BB + b)) * QQ + q;
        float m = g_mpart[pidx];
        float S = g_Spart[pidx];
        float M = m;
#pragma unroll
        for (int off = 16; off; off >>= 1)
            M = fmaxf(M, __shfl_xor_sync(0xffffffffu, M, off));
        float e = (m > -1e29f) ? __expf(m - M) : 0.0f;
        float d = e * S;
#pragma unroll
        for (int off = 16; off; off >>= 1)
            d += __shfl_xor_sync(0xffffffffu, d, off);
        s_wt[tid] = e * __fdividef(1.0f, d);
    }
    __syncthreads();

    float acc = 0.0f;
#pragma unroll
    for (int s = 0; s < SPLITS; s++) {
        acc = fmaf(s_wt[s], g_Opart[(((size_t)(s * BB + b)) * QQ + q) * DV + tid], acc);
    }
    out[((size_t)(b * QQ + q)) * DV + tid] = acc;
}

// ---------------------------------------------------------------------------
// Launch
// ---------------------------------------------------------------------------
extern "C" void kernel_launch(void* const* d_in, const int* in_sizes, int n_in,
                              void* d_out, int out_size) {
    const float* queries = (const float*)d_in[0];
    const float* keys    = (const float*)d_in[1];
    const float* values  = (const float*)d_in[2];
    const int*   valid_lens = (const int*)d_in[3];
    const float* Wq = (const float*)d_in[4];
    const float* Wk = (const float*)d_in[5];
    const float* Wv = (const float*)d_in[6];
    float* out = (float*)d_out;

    (void)in_sizes; (void)n_in; (void)out_size;

    const int smem_bytes = (QTILE * 260 + 256 + KPC * 256 + QTILE * PPAD + 256 + 256 + 32) * 4;
    cudaFuncSetAttribute(flash_kernel, cudaFuncAttributeMaxDynamicSharedMemorySize, smem_bytes);

    gemm_proj_kernel<<<dim3(HH / PN, (BB * QQ) / PM + (BB * KK) / PM), 256>>>(queries, keys, Wq, Wk);
    flash_kernel<<<dim3(SPLITS, QQ / QTILE, BB), 256, smem_bytes>>>(values, Wv, valid_lens);
    combine_kernel<<<dim3(QQ, BB), 256>>>(out);
}